// round 11
// baseline (speedup 1.0000x reference)
#include <cuda_runtime.h>

// ---------------------------------------------------------------------------
// ChildHAggregation: B=32768, HALF=512, DIM=1024
// out = hidden + leaf, where
//   q = (hlr@qU + qU_b) * (xh@qWu + qWu_b) + (xh@qWb + qWb_b)      (B,2,512)
//   k = likewise with kU/kWu/kWb
//   scores = softmax(q k^T / sqrt(512))                             (B,2,2)
//   x = [hl,hr] + (scores @ [hl;hr]).reshape(B,1024)
//   x = alpha*(x-mean)/(std_ddof1 + 1e-6) + beta
//   hidden = (x@hU + hU_b) * (xh@hWu + hWu_b) + (xh@hWb + hWb_b)
//   leaf   = (xw@lU + lU_b) * (xh@lWu + lWu_b) + (xh@lWb + lWb_b)
// ---------------------------------------------------------------------------

#define MAXB 32768

// Scratch (device globals: allocation rules forbid cudaMalloc)
__device__ float g_Q [MAXB * 1024];   // (B,2,512)
__device__ float g_K [MAXB * 1024];   // (B,2,512)
__device__ float g_U1[MAXB * 512];    // gate mul
__device__ float g_U2[MAXB * 512];    // gate add
__device__ float g_XN[MAXB * 1024];   // layernormed x

typedef unsigned long long u64;

__device__ __forceinline__ u64 pk2(float x, float y) {
    u64 r; asm("mov.b64 %0, {%1, %2};" : "=l"(r) : "f"(x), "f"(y)); return r;
}
__device__ __forceinline__ void upk2(u64 v, float &x, float &y) {
    asm("mov.b64 {%0, %1}, %2;" : "=f"(x), "=f"(y) : "l"(v));
}
// Blackwell packed fp32 FMA (SASS FFMA2) — 2 MACs per fma-pipe issue.
__device__ __forceinline__ void fma2(u64 &d, u64 a, u64 b) {
    asm("fma.rn.f32x2 %0, %1, %2, %0;" : "+l"(d) : "l"(a), "l"(b));
}

// ---------------------------------------------------------------------------
// Generic fused GEMM: C[M,512] = epilogue(A[M,K] @ W[K,512])
//   mode 0: C  =  acc + bias
//   mode 1: C  = (acc + bias) * mulv[row,col] + addv[row,col]
//   mode 2: C += (acc + bias) * mulv[row,col] + addv[row,col]
// 64x64 tile, BK=16, 256 threads, 4x4 micro-tile on f32x2 accumulators.
// All dims (M=32768, N=512, K in {512,1024}) divide the tiles exactly.
// ---------------------------------------------------------------------------
#define SPAD 68   // row stride in floats (272B: 16B-aligned, staggers banks)

__global__ __launch_bounds__(256) void gemm_kernel(
    const float* __restrict__ A, int lda,
    const float* __restrict__ W,          // K x 512, row-major
    const float* __restrict__ bias,       // 512
    const float* __restrict__ mulv,       // B x 512 or nullptr
    const float* __restrict__ addv,       // B x 512 or nullptr
    float* __restrict__ C, int ldc,
    int K, int mode)
{
    __shared__ __align__(16) float As[16][SPAD];  // [k][m]
    __shared__ __align__(16) float Bs[16][SPAD];  // [k][n]

    const int tid = threadIdx.x;
    const int bm = blockIdx.y * 64;
    const int bn = blockIdx.x * 64;

    // loader mapping
    const int arow = tid >> 2;             // 0..63
    const int akq  = (tid & 3) << 2;       // 0,4,8,12
    const int wkr  = tid >> 4;             // 0..15
    const int wnq  = (tid & 15) << 2;      // 0..60

    // compute mapping
    const int tx = tid & 15;               // col group
    const int ty = tid >> 4;               // row group

    u64 acc[4][2];
    #pragma unroll
    for (int i = 0; i < 4; i++) { acc[i][0] = 0ull; acc[i][1] = 0ull; }

    const float* Aptr = A + (size_t)(bm + arow) * lda + akq;
    const float* Wptr = W + (size_t)wkr * 512 + bn + wnq;

    float4 av = *(const float4*)(Aptr);
    float4 wv = *(const float4*)(Wptr);

    for (int kk = 0; kk < K; kk += 16) {
        As[akq + 0][arow] = av.x;
        As[akq + 1][arow] = av.y;
        As[akq + 2][arow] = av.z;
        As[akq + 3][arow] = av.w;
        *(float4*)&Bs[wkr][wnq] = wv;
        __syncthreads();

        if (kk + 16 < K) {   // prefetch next panel (overlaps with compute)
            av = *(const float4*)(Aptr + kk + 16);
            wv = *(const float4*)(Wptr + (size_t)(kk + 16) * 512);
        }

        #pragma unroll
        for (int k = 0; k < 16; k++) {
            float4 a4 = *(const float4*)&As[k][ty * 4];
            ulonglong2 b2 = *(const ulonglong2*)&Bs[k][tx * 4];
            u64 a0 = pk2(a4.x, a4.x);
            u64 a1 = pk2(a4.y, a4.y);
            u64 a2 = pk2(a4.z, a4.z);
            u64 a3 = pk2(a4.w, a4.w);
            fma2(acc[0][0], a0, b2.x); fma2(acc[0][1], a0, b2.y);
            fma2(acc[1][0], a1, b2.x); fma2(acc[1][1], a1, b2.y);
            fma2(acc[2][0], a2, b2.x); fma2(acc[2][1], a2, b2.y);
            fma2(acc[3][0], a3, b2.x); fma2(acc[3][1], a3, b2.y);
        }
        __syncthreads();
    }

    // epilogue
    const int cn = bn + tx * 4;
    const float4 bb = *(const float4*)&bias[cn];
    #pragma unroll
    for (int i = 0; i < 4; i++) {
        const int row = bm + ty * 4 + i;
        float v0, v1, v2, v3;
        upk2(acc[i][0], v0, v1);
        upk2(acc[i][1], v2, v3);
        v0 += bb.x; v1 += bb.y; v2 += bb.z; v3 += bb.w;
        if (mode >= 1) {
            const float4 mv = *(const float4*)&mulv[(size_t)row * 512 + cn];
            const float4 ad = *(const float4*)&addv[(size_t)row * 512 + cn];
            v0 = v0 * mv.x + ad.x;
            v1 = v1 * mv.y + ad.y;
            v2 = v2 * mv.z + ad.z;
            v3 = v3 * mv.w + ad.w;
        }
        float* cp = C + (size_t)row * ldc + cn;
        if (mode == 2) {
            const float4 old = *(const float4*)cp;
            v0 += old.x; v1 += old.y; v2 += old.z; v3 += old.w;
        }
        *(float4*)cp = make_float4(v0, v1, v2, v3);
    }
}

// ---------------------------------------------------------------------------
// Attention (2x2) + residual + LayerNorm(ddof=1). One CTA per row.
// Reads g_Q/g_K (B,2,512), hl/hr; writes g_XN (B,1024).
// ---------------------------------------------------------------------------
__global__ __launch_bounds__(256) void attn_ln_kernel(
    const float* __restrict__ hl, const float* __restrict__ hr,
    const float* __restrict__ alpha, const float* __restrict__ beta)
{
    const int b = blockIdx.x;
    const int tid = threadIdx.x;
    const int lane = tid & 31, warp = tid >> 5;

    const float* q0 = g_Q + (size_t)b * 1024;
    const float* q1 = q0 + 512;
    const float* k0 = g_K + (size_t)b * 1024;
    const float* k1 = k0 + 512;
    const float* hlp = hl + (size_t)b * 512;
    const float* hrp = hr + (size_t)b * 512;

    float s00 = 0.f, s01 = 0.f, s10 = 0.f, s11 = 0.f;
    for (int i = tid; i < 512; i += 256) {
        const float a0 = q0[i], a1 = q1[i], c0 = k0[i], c1 = k1[i];
        s00 += a0 * c0; s01 += a0 * c1; s10 += a1 * c0; s11 += a1 * c1;
    }

    __shared__ float sm[8][4];
    __shared__ float probs[4];
    __shared__ float stats[2];

    #pragma unroll
    for (int o = 16; o; o >>= 1) {
        s00 += __shfl_down_sync(0xffffffffu, s00, o);
        s01 += __shfl_down_sync(0xffffffffu, s01, o);
        s10 += __shfl_down_sync(0xffffffffu, s10, o);
        s11 += __shfl_down_sync(0xffffffffu, s11, o);
    }
    if (lane == 0) { sm[warp][0] = s00; sm[warp][1] = s01; sm[warp][2] = s10; sm[warp][3] = s11; }
    __syncthreads();
    if (tid == 0) {
        float t00 = 0.f, t01 = 0.f, t10 = 0.f, t11 = 0.f;
        #pragma unroll
        for (int w = 0; w < 8; w++) { t00 += sm[w][0]; t01 += sm[w][1]; t10 += sm[w][2]; t11 += sm[w][3]; }
        const float sc = 0.044194173824159216f;  // 1/sqrt(512)
        t00 *= sc; t01 *= sc; t10 *= sc; t11 *= sc;
        const float m0 = fmaxf(t00, t01);
        const float e0 = expf(t00 - m0), e1 = expf(t01 - m0);
        const float r0 = 1.0f / (e0 + e1);
        probs[0] = e0 * r0; probs[1] = e1 * r0;
        const float m1 = fmaxf(t10, t11);
        const float f0 = expf(t10 - m1), f1 = expf(t11 - m1);
        const float r1 = 1.0f / (f0 + f1);
        probs[2] = f0 * r1; probs[3] = f1 * r1;
    }
    __syncthreads();
    const float p00 = probs[0], p01 = probs[1], p10 = probs[2], p11 = probs[3];

    float xv[4];
    float sum = 0.f, sq = 0.f;
    #pragma unroll
    for (int t = 0; t < 4; t++) {
        const int idx = tid + t * 256;
        const int j = idx & 511;
        const float l = hlp[j], r = hrp[j];
        const float v = (idx < 512) ? (l + p00 * l + p01 * r)
                                    : (r + p10 * l + p11 * r);
        xv[t] = v; sum += v; sq += v * v;
    }
    #pragma unroll
    for (int o = 16; o; o >>= 1) {
        sum += __shfl_down_sync(0xffffffffu, sum, o);
        sq  += __shfl_down_sync(0xffffffffu, sq, o);
    }
    if (lane == 0) { sm[warp][0] = sum; sm[warp][1] = sq; }
    __syncthreads();
    if (tid == 0) {
        float S = 0.f, Q = 0.f;
        #pragma unroll
        for (int w = 0; w < 8; w++) { S += sm[w][0]; Q += sm[w][1]; }
        const float mean = S * (1.0f / 1024.0f);
        float var = (Q - 1024.0f * mean * mean) * (1.0f / 1023.0f);
        var = fmaxf(var, 0.0f);
        stats[0] = mean;
        stats[1] = 1.0f / (sqrtf(var) + 1e-6f);
    }
    __syncthreads();
    const float mean = stats[0], inv = stats[1];

    float* xnp = g_XN + (size_t)b * 1024;
    #pragma unroll
    for (int t = 0; t < 4; t++) {
        const int idx = tid + t * 256;
        xnp[idx] = alpha[idx] * (xv[t] - mean) * inv + beta[idx];
    }
}

// ---------------------------------------------------------------------------
extern "C" void kernel_launch(void* const* d_in, const int* in_sizes, int n_in,
                              void* d_out, int out_size)
{
    const float* hl    = (const float*)d_in[0];
    const float* hr    = (const float*)d_in[1];
    const float* xw    = (const float*)d_in[2];
    const float* xh    = (const float*)d_in[3];
    const float* qU_w  = (const float*)d_in[4];
    const float* qU_b  = (const float*)d_in[5];
    const float* qWu_w = (const float*)d_in[6];
    const float* qWu_b = (const float*)d_in[7];
    const float* qWb_w = (const float*)d_in[8];
    const float* qWb_b = (const float*)d_in[9];
    const float* kU_w  = (const float*)d_in[10];
    const float* kU_b  = (const float*)d_in[11];
    const float* kWu_w = (const float*)d_in[12];
    const float* kWu_b = (const float*)d_in[13];
    const float* kWb_w = (const float*)d_in[14];
    const float* kWb_b = (const float*)d_in[15];
    const float* alpha = (const float*)d_in[16];
    const float* beta  = (const float*)d_in[17];
    const float* hU_w  = (const float*)d_in[18];
    const float* hU_b  = (const float*)d_in[19];
    const float* hWu_w = (const float*)d_in[20];
    const float* hWu_b = (const float*)d_in[21];
    const float* hWb_w = (const float*)d_in[22];
    const float* hWb_b = (const float*)d_in[23];
    const float* lU_w  = (const float*)d_in[24];
    const float* lU_b  = (const float*)d_in[25];
    const float* lWu_w = (const float*)d_in[26];
    const float* lWu_b = (const float*)d_in[27];
    const float* lWb_w = (const float*)d_in[28];
    const float* lWb_b = (const float*)d_in[29];
    float* out = (float*)d_out;

    const int B = in_sizes[0] / 512;

    float *Qb, *Kb, *U1, *U2, *XN;
    cudaGetSymbolAddress((void**)&Qb, g_Q);
    cudaGetSymbolAddress((void**)&Kb, g_K);
    cudaGetSymbolAddress((void**)&U1, g_U1);
    cudaGetSymbolAddress((void**)&U2, g_U2);
    cudaGetSymbolAddress((void**)&XN, g_XN);

    dim3 blk(256);
    dim3 grd(512 / 64, B / 64);

    // --- q = (hlr@qU + b) * (xh@qWu + b) + (xh@qWb + b) ---
    gemm_kernel<<<grd, blk>>>(xh, 512, qWu_w, qWu_b, nullptr, nullptr, U1, 512, 512, 0);
    gemm_kernel<<<grd, blk>>>(xh, 512, qWb_w, qWb_b, nullptr, nullptr, U2, 512, 512, 0);
    gemm_kernel<<<grd, blk>>>(hl, 512, qU_w,  qU_b,  U1, U2, Qb,       1024, 512, 1);
    gemm_kernel<<<grd, blk>>>(hr, 512, qU_w,  qU_b,  U1, U2, Qb + 512, 1024, 512, 1);
    // --- k ---
    gemm_kernel<<<grd, blk>>>(xh, 512, kWu_w, kWu_b, nullptr, nullptr, U1, 512, 512, 0);
    gemm_kernel<<<grd, blk>>>(xh, 512, kWb_w, kWb_b, nullptr, nullptr, U2, 512, 512, 0);
    gemm_kernel<<<grd, blk>>>(hl, 512, kU_w,  kU_b,  U1, U2, Kb,       1024, 512, 1);
    gemm_kernel<<<grd, blk>>>(hr, 512, kU_w,  kU_b,  U1, U2, Kb + 512, 1024, 512, 1);

    // --- 2x2 attention + residual + layernorm -> g_XN ---
    attn_ln_kernel<<<B, 256>>>(hl, hr, alpha, beta);

    // --- hidden -> out ---
    gemm_kernel<<<grd, blk>>>(xh, 512,  hWu_w, hWu_b, nullptr, nullptr, U1, 512, 512, 0);
    gemm_kernel<<<grd, blk>>>(xh, 512,  hWb_w, hWb_b, nullptr, nullptr, U2, 512, 512, 0);
    gemm_kernel<<<grd, blk>>>(XN, 1024, hU_w,  hU_b,  U1, U2, out, 512, 1024, 1);

    // --- leaf, accumulated into out ---
    gemm_kernel<<<grd, blk>>>(xh, 512,  lWu_w, lWu_b, nullptr, nullptr, U1, 512, 512, 0);
    gemm_kernel<<<grd, blk>>>(xh, 512,  lWb_w, lWb_b, nullptr, nullptr, U2, 512, 512, 0);
    gemm_kernel<<<grd, blk>>>(xw, 1024, lU_w,  lU_b,  U1, U2, out, 512, 1024, 2);
}

// round 12
// speedup vs baseline: 1.0046x; 1.0046x over previous
#include <cuda_runtime.h>

// ---------------------------------------------------------------------------
// ChildHAggregation: B=32768, HALF=512, DIM=1024
// out = hidden + leaf, where
//   q = (hlr@qU + qU_b) * (xh@qWu + qWu_b) + (xh@qWb + qWb_b)      (B,2,512)
//   k = likewise with kU/kWu/kWb
//   scores = softmax(q k^T / sqrt(512))                             (B,2,2)
//   x = [hl,hr] + (scores @ [hl;hr]).reshape(B,1024)
//   x = alpha*(x-mean)/(std_ddof1 + 1e-6) + beta
//   hidden = (x@hU + hU_b) * (xh@hWu + hWu_b) + (xh@hWb + hWb_b)
//   leaf   = (xw@lU + lU_b) * (xh@lWu + lWu_b) + (xh@lWb + lWb_b)
// ---------------------------------------------------------------------------

#define MAXB 32768

// Scratch (device globals: allocation rules forbid cudaMalloc)
__device__ float g_Q [MAXB * 1024];   // (B,2,512)
__device__ float g_K [MAXB * 1024];   // (B,2,512)
__device__ float g_U1[MAXB * 512];    // gate mul
__device__ float g_U2[MAXB * 512];    // gate add
__device__ float g_XN[MAXB * 1024];   // layernormed x

typedef unsigned long long u64;

__device__ __forceinline__ u64 pk2(float x, float y) {
    u64 r; asm("mov.b64 %0, {%1, %2};" : "=l"(r) : "f"(x), "f"(y)); return r;
}
__device__ __forceinline__ void upk2(u64 v, float &x, float &y) {
    asm("mov.b64 {%0, %1}, %2;" : "=f"(x), "=f"(y) : "l"(v));
}
// Blackwell packed fp32 FMA (SASS FFMA2) — 2 MACs per fma-pipe issue.
__device__ __forceinline__ void fma2(u64 &d, u64 a, u64 b) {
    asm("fma.rn.f32x2 %0, %1, %2, %0;" : "+l"(d) : "l"(a), "l"(b));
}

// ---------------------------------------------------------------------------
// Generic fused GEMM: C[M,512] = epilogue(A[M,K] @ W[K,512])
//   mode 0: C  =  acc + bias
//   mode 1: C  = (acc + bias) * mulv[row,col] + addv[row,col]
//   mode 2: C += (acc + bias) * mulv[row,col] + addv[row,col]
// 64x64 tile, BK=16, 256 threads, 4x4 micro-tile on f32x2 accumulators.
// All dims (M=32768, N=512, K in {512,1024}) divide the tiles exactly.
// ---------------------------------------------------------------------------
#define SPAD 68   // row stride in floats (272B: 16B-aligned, staggers banks)

__global__ __launch_bounds__(256) void gemm_kernel(
    const float* __restrict__ A, int lda,
    const float* __restrict__ W,          // K x 512, row-major
    const float* __restrict__ bias,       // 512
    const float* __restrict__ mulv,       // B x 512 or nullptr
    const float* __restrict__ addv,       // B x 512 or nullptr
    float* __restrict__ C, int ldc,
    int K, int mode)
{
    __shared__ __align__(16) float As[16][SPAD];  // [k][m]
    __shared__ __align__(16) float Bs[16][SPAD];  // [k][n]

    const int tid = threadIdx.x;
    const int bm = blockIdx.y * 64;
    const int bn = blockIdx.x * 64;

    // loader mapping
    const int arow = tid >> 2;             // 0..63
    const int akq  = (tid & 3) << 2;       // 0,4,8,12
    const int wkr  = tid >> 4;             // 0..15
    const int wnq  = (tid & 15) << 2;      // 0..60

    // compute mapping
    const int tx = tid & 15;               // col group
    const int ty = tid >> 4;               // row group

    u64 acc[4][2];
    #pragma unroll
    for (int i = 0; i < 4; i++) { acc[i][0] = 0ull; acc[i][1] = 0ull; }

    const float* Aptr = A + (size_t)(bm + arow) * lda + akq;
    const float* Wptr = W + (size_t)wkr * 512 + bn + wnq;

    float4 av = *(const float4*)(Aptr);
    float4 wv = *(const float4*)(Wptr);

    for (int kk = 0; kk < K; kk += 16) {
        As[akq + 0][arow] = av.x;
        As[akq + 1][arow] = av.y;
        As[akq + 2][arow] = av.z;
        As[akq + 3][arow] = av.w;
        *(float4*)&Bs[wkr][wnq] = wv;
        __syncthreads();

        if (kk + 16 < K) {   // prefetch next panel (overlaps with compute)
            av = *(const float4*)(Aptr + kk + 16);
            wv = *(const float4*)(Wptr + (size_t)(kk + 16) * 512);
        }

        #pragma unroll
        for (int k = 0; k < 16; k++) {
            float4 a4 = *(const float4*)&As[k][ty * 4];
            ulonglong2 b2 = *(const ulonglong2*)&Bs[k][tx * 4];
            u64 a0 = pk2(a4.x, a4.x);
            u64 a1 = pk2(a4.y, a4.y);
            u64 a2 = pk2(a4.z, a4.z);
            u64 a3 = pk2(a4.w, a4.w);
            fma2(acc[0][0], a0, b2.x); fma2(acc[0][1], a0, b2.y);
            fma2(acc[1][0], a1, b2.x); fma2(acc[1][1], a1, b2.y);
            fma2(acc[2][0], a2, b2.x); fma2(acc[2][1], a2, b2.y);
            fma2(acc[3][0], a3, b2.x); fma2(acc[3][1], a3, b2.y);
        }
        __syncthreads();
    }

    // epilogue
    const int cn = bn + tx * 4;
    const float4 bb = *(const float4*)&bias[cn];
    #pragma unroll
    for (int i = 0; i < 4; i++) {
        const int row = bm + ty * 4 + i;
        float v0, v1, v2, v3;
        upk2(acc[i][0], v0, v1);
        upk2(acc[i][1], v2, v3);
        v0 += bb.x; v1 += bb.y; v2 += bb.z; v3 += bb.w;
        if (mode >= 1) {
            const float4 mv = *(const float4*)&mulv[(size_t)row * 512 + cn];
            const float4 ad = *(const float4*)&addv[(size_t)row * 512 + cn];
            v0 = v0 * mv.x + ad.x;
            v1 = v1 * mv.y + ad.y;
            v2 = v2 * mv.z + ad.z;
            v3 = v3 * mv.w + ad.w;
        }
        float* cp = C + (size_t)row * ldc + cn;
        if (mode == 2) {
            const float4 old = *(const float4*)cp;
            v0 += old.x; v1 += old.y; v2 += old.z; v3 += old.w;
        }
        *(float4*)cp = make_float4(v0, v1, v2, v3);
    }
}

// ---------------------------------------------------------------------------
// Attention (2x2) + residual + LayerNorm(ddof=1). One CTA per row.
// Reads g_Q/g_K (B,2,512), hl/hr; writes g_XN (B,1024).
// ---------------------------------------------------------------------------
__global__ __launch_bounds__(256) void attn_ln_kernel(
    const float* __restrict__ hl, const float* __restrict__ hr,
    const float* __restrict__ alpha, const float* __restrict__ beta)
{
    const int b = blockIdx.x;
    const int tid = threadIdx.x;
    const int lane = tid & 31, warp = tid >> 5;

    const float* q0 = g_Q + (size_t)b * 1024;
    const float* q1 = q0 + 512;
    const float* k0 = g_K + (size_t)b * 1024;
    const float* k1 = k0 + 512;
    const float* hlp = hl + (size_t)b * 512;
    const float* hrp = hr + (size_t)b * 512;

    float s00 = 0.f, s01 = 0.f, s10 = 0.f, s11 = 0.f;
    for (int i = tid; i < 512; i += 256) {
        const float a0 = q0[i], a1 = q1[i], c0 = k0[i], c1 = k1[i];
        s00 += a0 * c0; s01 += a0 * c1; s10 += a1 * c0; s11 += a1 * c1;
    }

    __shared__ float sm[8][4];
    __shared__ float probs[4];
    __shared__ float stats[2];

    #pragma unroll
    for (int o = 16; o; o >>= 1) {
        s00 += __shfl_down_sync(0xffffffffu, s00, o);
        s01 += __shfl_down_sync(0xffffffffu, s01, o);
        s10 += __shfl_down_sync(0xffffffffu, s10, o);
        s11 += __shfl_down_sync(0xffffffffu, s11, o);
    }
    if (lane == 0) { sm[warp][0] = s00; sm[warp][1] = s01; sm[warp][2] = s10; sm[warp][3] = s11; }
    __syncthreads();
    if (tid == 0) {
        float t00 = 0.f, t01 = 0.f, t10 = 0.f, t11 = 0.f;
        #pragma unroll
        for (int w = 0; w < 8; w++) { t00 += sm[w][0]; t01 += sm[w][1]; t10 += sm[w][2]; t11 += sm[w][3]; }
        const float sc = 0.044194173824159216f;  // 1/sqrt(512)
        t00 *= sc; t01 *= sc; t10 *= sc; t11 *= sc;
        const float m0 = fmaxf(t00, t01);
        const float e0 = expf(t00 - m0), e1 = expf(t01 - m0);
        const float r0 = 1.0f / (e0 + e1);
        probs[0] = e0 * r0; probs[1] = e1 * r0;
        const float m1 = fmaxf(t10, t11);
        const float f0 = expf(t10 - m1), f1 = expf(t11 - m1);
        const float r1 = 1.0f / (f0 + f1);
        probs[2] = f0 * r1; probs[3] = f1 * r1;
    }
    __syncthreads();
    const float p00 = probs[0], p01 = probs[1], p10 = probs[2], p11 = probs[3];

    float xv[4];
    float sum = 0.f, sq = 0.f;
    #pragma unroll
    for (int t = 0; t < 4; t++) {
        const int idx = tid + t * 256;
        const int j = idx & 511;
        const float l = hlp[j], r = hrp[j];
        const float v = (idx < 512) ? (l + p00 * l + p01 * r)
                                    : (r + p10 * l + p11 * r);
        xv[t] = v; sum += v; sq += v * v;
    }
    #pragma unroll
    for (int o = 16; o; o >>= 1) {
        sum += __shfl_down_sync(0xffffffffu, sum, o);
        sq  += __shfl_down_sync(0xffffffffu, sq, o);
    }
    if (lane == 0) { sm[warp][0] = sum; sm[warp][1] = sq; }
    __syncthreads();
    if (tid == 0) {
        float S = 0.f, Q = 0.f;
        #pragma unroll
        for (int w = 0; w < 8; w++) { S += sm[w][0]; Q += sm[w][1]; }
        const float mean = S * (1.0f / 1024.0f);
        float var = (Q - 1024.0f * mean * mean) * (1.0f / 1023.0f);
        var = fmaxf(var, 0.0f);
        stats[0] = mean;
        stats[1] = 1.0f / (sqrtf(var) + 1e-6f);
    }
    __syncthreads();
    const float mean = stats[0], inv = stats[1];

    float* xnp = g_XN + (size_t)b * 1024;
    #pragma unroll
    for (int t = 0; t < 4; t++) {
        const int idx = tid + t * 256;
        xnp[idx] = alpha[idx] * (xv[t] - mean) * inv + beta[idx];
    }
}

// ---------------------------------------------------------------------------
extern "C" void kernel_launch(void* const* d_in, const int* in_sizes, int n_in,
                              void* d_out, int out_size)
{
    const float* hl    = (const float*)d_in[0];
    const float* hr    = (const float*)d_in[1];
    const float* xw    = (const float*)d_in[2];
    const float* xh    = (const float*)d_in[3];
    const float* qU_w  = (const float*)d_in[4];
    const float* qU_b  = (const float*)d_in[5];
    const float* qWu_w = (const float*)d_in[6];
    const float* qWu_b = (const float*)d_in[7];
    const float* qWb_w = (const float*)d_in[8];
    const float* qWb_b = (const float*)d_in[9];
    const float* kU_w  = (const float*)d_in[10];
    const float* kU_b  = (const float*)d_in[11];
    const float* kWu_w = (const float*)d_in[12];
    const float* kWu_b = (const float*)d_in[13];
    const float* kWb_w = (const float*)d_in[14];
    const float* kWb_b = (const float*)d_in[15];
    const float* alpha = (const float*)d_in[16];
    const float* beta  = (const float*)d_in[17];
    const float* hU_w  = (const float*)d_in[18];
    const float* hU_b  = (const float*)d_in[19];
    const float* hWu_w = (const float*)d_in[20];
    const float* hWu_b = (const float*)d_in[21];
    const float* hWb_w = (const float*)d_in[22];
    const float* hWb_b = (const float*)d_in[23];
    const float* lU_w  = (const float*)d_in[24];
    const float* lU_b  = (const float*)d_in[25];
    const float* lWu_w = (const float*)d_in[26];
    const float* lWu_b = (const float*)d_in[27];
    const float* lWb_w = (const float*)d_in[28];
    const float* lWb_b = (const float*)d_in[29];
    float* out = (float*)d_out;

    const int B = in_sizes[0] / 512;

    float *Qb, *Kb, *U1, *U2, *XN;
    cudaGetSymbolAddress((void**)&Qb, g_Q);
    cudaGetSymbolAddress((void**)&Kb, g_K);
    cudaGetSymbolAddress((void**)&U1, g_U1);
    cudaGetSymbolAddress((void**)&U2, g_U2);
    cudaGetSymbolAddress((void**)&XN, g_XN);

    dim3 blk(256);
    dim3 grd(512 / 64, B / 64);

    // --- q = (hlr@qU + b) * (xh@qWu + b) + (xh@qWb + b) ---
    gemm_kernel<<<grd, blk>>>(xh, 512, qWu_w, qWu_b, nullptr, nullptr, U1, 512, 512, 0);
    gemm_kernel<<<grd, blk>>>(xh, 512, qWb_w, qWb_b, nullptr, nullptr, U2, 512, 512, 0);
    gemm_kernel<<<grd, blk>>>(hl, 512, qU_w,  qU_b,  U1, U2, Qb,       1024, 512, 1);
    gemm_kernel<<<grd, blk>>>(hr, 512, qU_w,  qU_b,  U1, U2, Qb + 512, 1024, 512, 1);
    // --- k ---
    gemm_kernel<<<grd, blk>>>(xh, 512, kWu_w, kWu_b, nullptr, nullptr, U1, 512, 512, 0);
    gemm_kernel<<<grd, blk>>>(xh, 512, kWb_w, kWb_b, nullptr, nullptr, U2, 512, 512, 0);
    gemm_kernel<<<grd, blk>>>(hl, 512, kU_w,  kU_b,  U1, U2, Kb,       1024, 512, 1);
    gemm_kernel<<<grd, blk>>>(hr, 512, kU_w,  kU_b,  U1, U2, Kb + 512, 1024, 512, 1);

    // --- 2x2 attention + residual + layernorm -> g_XN ---
    attn_ln_kernel<<<B, 256>>>(hl, hr, alpha, beta);

    // --- hidden -> out ---
    gemm_kernel<<<grd, blk>>>(xh, 512,  hWu_w, hWu_b, nullptr, nullptr, U1, 512, 512, 0);
    gemm_kernel<<<grd, blk>>>(xh, 512,  hWb_w, hWb_b, nullptr, nullptr, U2, 512, 512, 0);
    gemm_kernel<<<grd, blk>>>(XN, 1024, hU_w,  hU_b,  U1, U2, out, 512, 1024, 1);

    // --- leaf, accumulated into out ---
    gemm_kernel<<<grd, blk>>>(xh, 512,  lWu_w, lWu_b, nullptr, nullptr, U1, 512, 512, 0);
    gemm_kernel<<<grd, blk>>>(xh, 512,  lWb_w, lWb_b, nullptr, nullptr, U2, 512, 512, 0);
    gemm_kernel<<<grd, blk>>>(xw, 1024, lU_w,  lU_b,  U1, U2, out, 512, 1024, 2);
}